// round 6
// baseline (speedup 1.0000x reference)
#include <cuda_runtime.h>
#include <math.h>
#include <stdint.h>

#define N_USERS   100000
#define N_RECIPES 50000
#define NE        600000
#define NL        200000
#define HDIM      128
#define OUTDIM    64

// ---------------- scratch (no allocation allowed) ----------------
__device__ __align__(128) float g_hu[(size_t)N_USERS * HDIM];
__device__ __align__(128) float g_hr[(size_t)N_RECIPES * HDIM];
__device__ __align__(128) float g_mean_r[(size_t)N_RECIPES * HDIM];
__device__ __align__(128) float g_mean_u[(size_t)N_USERS * HDIM];
__device__ __align__(128) float g_r1[(size_t)N_RECIPES * HDIM];
__device__ __align__(128) float g_u1[(size_t)N_USERS * HDIM];
__device__ __align__(128) float g_mr2[(size_t)N_RECIPES * HDIM];
__device__ __align__(128) float g_mu2[(size_t)N_USERS * HDIM];
__device__ __align__(128) float g_zr[(size_t)N_RECIPES * OUTDIM];
__device__ __align__(128) float g_zu[(size_t)N_USERS * OUTDIM];

__device__ __align__(128) int g_off_r[N_RECIPES + 1];
__device__ __align__(128) int g_off_u[N_USERS + 1];
__device__ __align__(128) int g_cur_r[N_RECIPES];
__device__ __align__(128) int g_cur_u[N_USERS];
__device__ __align__(128) int g_adj_r[NE];
__device__ __align__(128) int g_adj_u[NE];
__device__ __align__(128) int g_bsum_r[64];
__device__ __align__(128) int g_bsum_u[128];

// pre-rounded tf32 weights
#define W_TOTAL 147456
__device__ __align__(128) float g_wts[W_TOTAL];

// ---------------- tf32 mma helpers ----------------
__device__ __forceinline__ float f2tf32(float f) {
    uint32_t r;
    asm("cvt.rna.tf32.f32 %0, %1;" : "=r"(r) : "f"(f));
    return __uint_as_float(r);
}

__device__ __forceinline__ float4 cvt4(float4 v) {
    return make_float4(f2tf32(v.x), f2tf32(v.y), f2tf32(v.z), f2tf32(v.w));
}

__device__ __forceinline__ void mma_tf32(float* d,
                                         uint32_t a0, uint32_t a1, uint32_t a2, uint32_t a3,
                                         uint32_t b0, uint32_t b1) {
    asm volatile(
        "mma.sync.aligned.m16n8k8.row.col.f32.tf32.tf32.f32 "
        "{%0,%1,%2,%3}, {%4,%5,%6,%7}, {%8,%9}, {%0,%1,%2,%3};"
        : "+f"(d[0]), "+f"(d[1]), "+f"(d[2]), "+f"(d[3])
        : "r"(a0), "r"(a1), "r"(a2), "r"(a3), "r"(b0), "r"(b1));
}

__device__ __forceinline__ void cp_async16(uint32_t smem_dst, const void* gsrc) {
    asm volatile("cp.async.ca.shared.global [%0], [%1], 16;"
                 :: "r"(smem_dst), "l"(gsrc) : "memory");
}

// ---------------- weight prep ----------------
__global__ void prep_weights(const float* __restrict__ w0, const float* __restrict__ w1,
                             const float* __restrict__ w2, const float* __restrict__ w3,
                             const float* __restrict__ w4, const float* __restrict__ w5,
                             const float* __restrict__ w6, const float* __restrict__ w7,
                             const float* __restrict__ w8, const float* __restrict__ w9,
                             float* __restrict__ wts) {
    int i = blockIdx.x * blockDim.x + threadIdx.x;
    const float* src; int off;
    if      (i <  16384) { src = w0; off = 0;      }
    else if (i <  49152) { src = w1; off = 16384;  }
    else if (i <  65536) { src = w2; off = 49152;  }
    else if (i <  81920) { src = w3; off = 65536;  }
    else if (i <  98304) { src = w4; off = 81920;  }
    else if (i < 114688) { src = w5; off = 98304;  }
    else if (i < 122880) { src = w6; off = 114688; }
    else if (i < 131072) { src = w7; off = 122880; }
    else if (i < 139264) { src = w8; off = 131072; }
    else if (i < W_TOTAL){ src = w9; off = 139264; }
    else return;
    wts[i] = f2tf32(src[i - off]);
}

// ---------------- four-sided 128x64-tile tf32 GEMM ----------------
// side: out[n, 64(+ldo stride)] = A[n,*] @ WA^T (+ B @ WB^T) + bias (+relu)
struct GSide {
    const float *A, *WA, *B, *WB, *bias;
    float *out;
    int n, lda, ldwa, ldb, ldwb, nch, cha, ldo;
};

struct GQuad {
    GSide s0, s1, s2, s3;
    int sp1, sp2, sp3;
};

template <bool RELU>
__global__ __launch_bounds__(256, 2)
void gemm_mma(GQuad q) {
    constexpr int J   = 64;
    constexpr int LDS = 36;
    constexpr int NT  = 4;                  // J/16
    constexpr int WI  = 2;                  // (J*8)/256

    extern __shared__ float sm[];
    float* AsB = sm;                        // [2][128][LDS]
    float* WsB = sm + 2 * 128 * LDS;        // [2][J][LDS]

    GSide s; int bid;
    if ((int)blockIdx.x < q.sp1)      { s = q.s0; bid = blockIdx.x; }
    else if ((int)blockIdx.x < q.sp2) { s = q.s1; bid = blockIdx.x - q.sp1; }
    else if ((int)blockIdx.x < q.sp3) { s = q.s2; bid = blockIdx.x - q.sp2; }
    else                              { s = q.s3; bid = blockIdx.x - q.sp3; }
    const int row0 = bid * 128;

    const int tid  = threadIdx.x;
    const int lane = tid & 31;
    const int wid  = tid >> 5;
    const int wm   = wid & 3;
    const int wn   = wid >> 2;
    const int qr   = lane >> 2;
    const int qc   = lane & 3;

    float acc[2][NT][4];
    #pragma unroll
    for (int mt = 0; mt < 2; mt++)
        #pragma unroll
        for (int nt = 0; nt < NT; nt++)
            #pragma unroll
            for (int qq = 0; qq < 4; qq++) acc[mt][nt][qq] = 0.f;

    float4 pa[4];

    auto fetchA = [&](int c) {
        const float* src = (c < s.cha) ? s.A : s.B;
        const int ld = (c < s.cha) ? s.lda : s.ldb;
        const int k0 = ((c < s.cha) ? c : c - s.cha) * 32;
        #pragma unroll
        for (int i = 0; i < 4; i++) {
            int lin = tid + i * 256;
            int r = lin >> 3, qk = lin & 7;
            int gr = row0 + r;
            pa[i] = (gr < s.n)
                ? *reinterpret_cast<const float4*>(&src[(size_t)gr * ld + k0 + qk * 4])
                : make_float4(0.f, 0.f, 0.f, 0.f);
        }
    };

    auto issueW = [&](int c, int b) {
        const float* w = (c < s.cha) ? s.WA : s.WB;
        const int ld = (c < s.cha) ? s.ldwa : s.ldwb;
        const int k0 = ((c < s.cha) ? c : c - s.cha) * 32;
        uint32_t wbase = (uint32_t)__cvta_generic_to_shared(WsB + b * J * LDS);
        #pragma unroll
        for (int i = 0; i < WI; i++) {
            int lin = tid + i * 256;
            int j = lin >> 3, qk = lin & 7;
            cp_async16(wbase + (uint32_t)(j * LDS + qk * 4) * 4,
                       &w[(size_t)j * ld + k0 + qk * 4]);
        }
        asm volatile("cp.async.commit_group;" ::: "memory");
    };

    auto storeA = [&](int b) {
        float* as = AsB + b * 128 * LDS;
        #pragma unroll
        for (int i = 0; i < 4; i++) {
            int lin = tid + i * 256;
            int r = lin >> 3, qk = lin & 7;
            *reinterpret_cast<float4*>(&as[r * LDS + qk * 4]) = cvt4(pa[i]);
        }
    };

    const int nch = s.nch;
    fetchA(0);
    issueW(0, 0);
    storeA(0);
    asm volatile("cp.async.wait_group 0;" ::: "memory");
    __syncthreads();

    for (int c = 0; c < nch; ++c) {
        const int b = c & 1;
        if (c + 1 < nch) {
            fetchA(c + 1);
            issueW(c + 1, b ^ 1);
        }

        const float* as = AsB + b * 128 * LDS + (wm * 32) * LDS;
        const float* ws = WsB + b * J * LDS + (wn * NT * 8) * LDS;

        #pragma unroll
        for (int ks = 0; ks < 4; ++ks) {
            const int k0 = ks * 8 + qc;
            uint32_t af[2][4];
            #pragma unroll
            for (int mt = 0; mt < 2; mt++) {
                const float* ap = as + (mt * 16 + qr) * LDS;
                af[mt][0] = __float_as_uint(ap[k0]);
                af[mt][1] = __float_as_uint(ap[8 * LDS + k0]);
                af[mt][2] = __float_as_uint(ap[k0 + 4]);
                af[mt][3] = __float_as_uint(ap[8 * LDS + k0 + 4]);
            }
            uint32_t bf[NT][2];
            #pragma unroll
            for (int nt = 0; nt < NT; nt++) {
                const float* bp = ws + (nt * 8 + qr) * LDS;
                bf[nt][0] = __float_as_uint(bp[k0]);
                bf[nt][1] = __float_as_uint(bp[k0 + 4]);
            }
            #pragma unroll
            for (int mt = 0; mt < 2; mt++)
                #pragma unroll
                for (int nt = 0; nt < NT; nt++)
                    mma_tf32(acc[mt][nt],
                             af[mt][0], af[mt][1], af[mt][2], af[mt][3],
                             bf[nt][0], bf[nt][1]);
        }

        if (c + 1 < nch) {
            storeA(b ^ 1);
            asm volatile("cp.async.wait_group 0;" ::: "memory");
            __syncthreads();
        }
    }

    #pragma unroll
    for (int mt = 0; mt < 2; mt++) {
        #pragma unroll
        for (int nt = 0; nt < NT; nt++) {
            int gcol = wn * NT * 8 + nt * 8 + 2 * qc;
            float bx = __ldg(&s.bias[gcol]), by = __ldg(&s.bias[gcol + 1]);
            int r0 = row0 + wm * 32 + mt * 16 + qr;
            float v0 = acc[mt][nt][0] + bx, v1 = acc[mt][nt][1] + by;
            float v2 = acc[mt][nt][2] + bx, v3 = acc[mt][nt][3] + by;
            if (RELU) {
                v0 = fmaxf(v0, 0.f); v1 = fmaxf(v1, 0.f);
                v2 = fmaxf(v2, 0.f); v3 = fmaxf(v3, 0.f);
            }
            if (r0 < s.n)
                *reinterpret_cast<float2*>(&s.out[(size_t)r0 * s.ldo + gcol]) = make_float2(v0, v1);
            if (r0 + 8 < s.n)
                *reinterpret_cast<float2*>(&s.out[(size_t)(r0 + 8) * s.ldo + gcol]) = make_float2(v2, v3);
        }
    }
}

// ---------------- merged small utility kernels ----------------
__global__ void zero_int2(int* __restrict__ p0, int n0, int* __restrict__ p1, int n1) {
    int i = blockIdx.x * blockDim.x + threadIdx.x;
    if (i < n0) p0[i] = 0;
    else if (i < n0 + n1) p1[i - n0] = 0;
}

__global__ void copy_int2(int* __restrict__ d0, const int* __restrict__ s0, int n0,
                          int* __restrict__ d1, const int* __restrict__ s1, int n1) {
    int i = blockIdx.x * blockDim.x + threadIdx.x;
    if (i < n0) d0[i] = s0[i];
    else if (i < n0 + n1) d1[i - n0] = s1[i - n0];
}

__global__ void count_deg(const int* __restrict__ es, const int* __restrict__ ed,
                          int* __restrict__ deg_u, int* __restrict__ deg_r, int E) {
    int e = blockIdx.x * blockDim.x + threadIdx.x;
    if (e < E) {
        atomicAdd(&deg_u[es[e]], 1);
        atomicAdd(&deg_r[ed[e]], 1);
    }
}

__global__ void scan_chunks2(const int* __restrict__ dg0, int* __restrict__ of0,
                             int* __restrict__ bs0, int n0, int nb0,
                             const int* __restrict__ dg1, int* __restrict__ of1,
                             int* __restrict__ bs1, int n1) {
    const int* deg; int* off; int* bsum; int n, lb;
    if ((int)blockIdx.x < nb0) { deg = dg0; off = of0; bsum = bs0; n = n0; lb = blockIdx.x; }
    else { deg = dg1; off = of1; bsum = bs1; n = n1; lb = blockIdx.x - nb0; }
    __shared__ int sh[1024];
    int t = threadIdx.x;
    int gid = lb * 1024 + t;
    int v = (gid < n) ? deg[gid] : 0;
    sh[t] = v;
    __syncthreads();
    #pragma unroll
    for (int d = 1; d < 1024; d <<= 1) {
        int add = (t >= d) ? sh[t - d] : 0;
        __syncthreads();
        sh[t] += add;
        __syncthreads();
    }
    if (gid < n) off[gid + 1] = sh[t];
    if (t == 1023) bsum[lb] = sh[1023];
    if (gid == 0) off[0] = 0;
}

__global__ void scan_bsums2(int* __restrict__ b0, int nb0, int* __restrict__ b1, int nb1) {
    if (threadIdx.x != 0) return;
    int* b = (blockIdx.x == 0) ? b0 : b1;
    int nb = (blockIdx.x == 0) ? nb0 : nb1;
    int acc = 0;
    for (int i = 0; i < nb; i++) { int t = b[i]; b[i] = acc; acc += t; }
}

__global__ void add_bsums2(int* __restrict__ of0, const int* __restrict__ bs0, int n0, int nb0,
                           int* __restrict__ of1, const int* __restrict__ bs1, int n1) {
    int* off; const int* bsum; int n, lb;
    if ((int)blockIdx.x < nb0) { off = of0; bsum = bs0; n = n0; lb = blockIdx.x; }
    else { off = of1; bsum = bs1; n = n1; lb = blockIdx.x - nb0; }
    int gid = lb * 1024 + threadIdx.x;
    if (gid < n) off[gid + 1] += bsum[lb];
}

__global__ void fill_adj(const int* __restrict__ es, const int* __restrict__ ed,
                         int* __restrict__ cur_u, int* __restrict__ cur_r,
                         int* __restrict__ adj_u, int* __restrict__ adj_r, int E) {
    int e = blockIdx.x * blockDim.x + threadIdx.x;
    if (e < E) {
        int s = es[e], d = ed[e];
        adj_r[atomicAdd(&cur_r[d], 1)] = s;
        adj_u[atomicAdd(&cur_u[s], 1)] = d;
    }
}

// ---------------- merged scatter-mean, 4-way unrolled gather ----------------
__global__ void aggregate_mean2(
    const float* __restrict__ f0, const int* __restrict__ o0,
    const int* __restrict__ a0, float* __restrict__ out0, int n0,
    const float* __restrict__ f1, const int* __restrict__ o1,
    const int* __restrict__ a1, float* __restrict__ out1, int n1) {
    int w = (blockIdx.x * blockDim.x + threadIdx.x) >> 5;
    const float* feat; const int* off; const int* adj; float* out;
    if (w < n0) { feat = f0; off = o0; adj = a0; out = out0; }
    else {
        w -= n0;
        if (w >= n1) return;
        feat = f1; off = o1; adj = a1; out = out1;
    }
    int lane = threadIdx.x & 31;
    int s = off[w], e = off[w + 1];
    float4 acc = make_float4(0.f, 0.f, 0.f, 0.f);
    int i = s;
    for (; i + 4 <= e; i += 4) {
        int nb0 = __ldg(&adj[i]);
        int nb1 = __ldg(&adj[i + 1]);
        int nb2 = __ldg(&adj[i + 2]);
        int nb3 = __ldg(&adj[i + 3]);
        float4 v0 = *reinterpret_cast<const float4*>(&feat[(size_t)nb0 * HDIM + lane * 4]);
        float4 v1 = *reinterpret_cast<const float4*>(&feat[(size_t)nb1 * HDIM + lane * 4]);
        float4 v2 = *reinterpret_cast<const float4*>(&feat[(size_t)nb2 * HDIM + lane * 4]);
        float4 v3 = *reinterpret_cast<const float4*>(&feat[(size_t)nb3 * HDIM + lane * 4]);
        acc.x += v0.x + v1.x + v2.x + v3.x;
        acc.y += v0.y + v1.y + v2.y + v3.y;
        acc.z += v0.z + v1.z + v2.z + v3.z;
        acc.w += v0.w + v1.w + v2.w + v3.w;
    }
    for (; i < e; i++) {
        int nb = __ldg(&adj[i]);
        float4 v = *reinterpret_cast<const float4*>(&feat[(size_t)nb * HDIM + lane * 4]);
        acc.x += v.x; acc.y += v.y; acc.z += v.z; acc.w += v.w;
    }
    float inv = (e > s) ? 1.f / (float)(e - s) : 0.f;
    acc.x *= inv; acc.y *= inv; acc.z *= inv; acc.w *= inv;
    *reinterpret_cast<float4*>(&out[(size_t)w * HDIM + lane * 4]) = acc;
}

// ---------------- decoder ----------------
__global__ void decoder_kernel(const float* __restrict__ zu, const float* __restrict__ zr,
                               const int* __restrict__ ls, const int* __restrict__ ld,
                               float* __restrict__ out, int L) {
    int w = (blockIdx.x * blockDim.x + threadIdx.x) >> 5;
    if (w >= L) return;
    int lane = threadIdx.x & 31;
    int s = __ldg(&ls[w]), d = __ldg(&ld[w]);
    float2 a = *reinterpret_cast<const float2*>(&zu[(size_t)s * OUTDIM + lane * 2]);
    float2 b = *reinterpret_cast<const float2*>(&zr[(size_t)d * OUTDIM + lane * 2]);
    float dot = a.x * b.x + a.y * b.y;
    float na = a.x * a.x + a.y * a.y;
    float nb = b.x * b.x + b.y * b.y;
    #pragma unroll
    for (int o = 16; o > 0; o >>= 1) {
        dot += __shfl_xor_sync(0xffffffffu, dot, o);
        na  += __shfl_xor_sync(0xffffffffu, na, o);
        nb  += __shfl_xor_sync(0xffffffffu, nb, o);
    }
    if (lane == 0)
        out[w] = dot / (fmaxf(sqrtf(na), 1e-12f) * fmaxf(sqrtf(nb), 1e-12f));
}

// ---------------- launch ----------------
extern "C" void kernel_launch(void* const* d_in, const int* in_sizes, int n_in,
                              void* d_out, int out_size) {
    const float* x_user   = (const float*)d_in[0];
    const float* x_recipe = (const float*)d_in[1];
    const int* edge_src = (const int*)d_in[2];
    const int* edge_dst = (const int*)d_in[3];
    const int* lbl_src  = (const int*)d_in[4];
    const int* lbl_dst  = (const int*)d_in[5];
    const float* Wu   = (const float*)d_in[6];
    const float* bu   = (const float*)d_in[7];
    const float* Wrec = (const float*)d_in[8];
    const float* brec = (const float*)d_in[9];
    const float* c1urWl = (const float*)d_in[10];
    const float* c1urbl = (const float*)d_in[11];
    const float* c1urWr = (const float*)d_in[12];
    const float* c1ruWl = (const float*)d_in[13];
    const float* c1rubl = (const float*)d_in[14];
    const float* c1ruWr = (const float*)d_in[15];
    const float* c2urWl = (const float*)d_in[16];
    const float* c2urbl = (const float*)d_in[17];
    const float* c2urWr = (const float*)d_in[18];
    const float* c2ruWl = (const float*)d_in[19];
    const float* c2rubl = (const float*)d_in[20];
    const float* c2ruWr = (const float*)d_in[21];
    float* out = (float*)d_out;

    float *hu, *hr, *mean_r, *mean_u, *r1, *u1, *mr2, *mu2, *zr, *zu, *wts;
    int *off_r, *off_u, *cur_r, *cur_u, *adj_r, *adj_u, *bs_r, *bs_u;
    cudaGetSymbolAddress((void**)&hu, g_hu);
    cudaGetSymbolAddress((void**)&hr, g_hr);
    cudaGetSymbolAddress((void**)&mean_r, g_mean_r);
    cudaGetSymbolAddress((void**)&mean_u, g_mean_u);
    cudaGetSymbolAddress((void**)&r1, g_r1);
    cudaGetSymbolAddress((void**)&u1, g_u1);
    cudaGetSymbolAddress((void**)&mr2, g_mr2);
    cudaGetSymbolAddress((void**)&mu2, g_mu2);
    cudaGetSymbolAddress((void**)&zr, g_zr);
    cudaGetSymbolAddress((void**)&zu, g_zu);
    cudaGetSymbolAddress((void**)&wts, g_wts);
    cudaGetSymbolAddress((void**)&off_r, g_off_r);
    cudaGetSymbolAddress((void**)&off_u, g_off_u);
    cudaGetSymbolAddress((void**)&cur_r, g_cur_r);
    cudaGetSymbolAddress((void**)&cur_u, g_cur_u);
    cudaGetSymbolAddress((void**)&adj_r, g_adj_r);
    cudaGetSymbolAddress((void**)&adj_u, g_adj_u);
    cudaGetSymbolAddress((void**)&bs_r, g_bsum_r);
    cudaGetSymbolAddress((void**)&bs_u, g_bsum_u);

    // tf32 weight views
    const float* tWu     = wts;
    const float* tWrec   = wts + 16384;
    const float* tc1urWl = wts + 49152;
    const float* tc1urWr = wts + 65536;
    const float* tc1ruWl = wts + 81920;
    const float* tc1ruWr = wts + 98304;
    const float* tc2urWl = wts + 114688;
    const float* tc2urWr = wts + 122880;
    const float* tc2ruWl = wts + 131072;
    const float* tc2ruWr = wts + 139264;

    const int SM_O = 2 * (128 * 36 + 64 * 36) * 4;   // 55296 B
    cudaFuncSetAttribute(gemm_mma<false>,
                         cudaFuncAttributeMaxDynamicSharedMemorySize, SM_O);
    cudaFuncSetAttribute(gemm_mma<true>,
                         cudaFuncAttributeMaxDynamicSharedMemorySize, SM_O);

    const int CH_U = (N_USERS + 1023) / 1024;    // 98
    const int CH_R = (N_RECIPES + 1023) / 1024;  // 49
    const int GB_U = (N_USERS + 127) / 128;      // 782
    const int GB_R = (N_RECIPES + 127) / 128;    // 391

    // --- GEMM quads (each J=128 layer = two column-half sides) ---
    auto mk = [](const float* A, const float* WA, const float* B, const float* WB,
                 const float* bias, float* o, int n, int lda, int ldw,
                 int nch, int cha, int ldo) {
        GSide g = { A, WA, B, WB, bias, o, n, lda, ldw, lda, ldw, nch, cha, ldo };
        return g;
    };

    GQuad proj;
    proj.s0 = mk(x_recipe, tWrec,       x_recipe + 128, tWrec + 128,       brec,      hr,      N_RECIPES, 256, 256, 8, 4, 128);
    proj.s1 = mk(x_recipe, tWrec + 64 * 256, x_recipe + 128, tWrec + 64 * 256 + 128, brec + 64, hr + 64, N_RECIPES, 256, 256, 8, 4, 128);
    proj.s2 = mk(x_user,   tWu,         x_user,         tWu,               bu,        hu,      N_USERS,   128, 128, 4, 4, 128);
    proj.s3 = mk(x_user,   tWu + 64 * 128, x_user,      tWu + 64 * 128,    bu + 64,   hu + 64, N_USERS,   128, 128, 4, 4, 128);
    proj.sp1 = GB_R; proj.sp2 = 2 * GB_R; proj.sp3 = 2 * GB_R + GB_U;
    const int PROJ_GRID = 2 * GB_R + 2 * GB_U;

    GQuad c1;
    c1.s0 = mk(mean_r, tc1urWl,            hr, tc1urWr,            c1urbl,      r1,      N_RECIPES, 128, 128, 8, 4, 128);
    c1.s1 = mk(mean_r, tc1urWl + 64 * 128, hr, tc1urWr + 64 * 128, c1urbl + 64, r1 + 64, N_RECIPES, 128, 128, 8, 4, 128);
    c1.s2 = mk(mean_u, tc1ruWl,            hu, tc1ruWr,            c1rubl,      u1,      N_USERS,   128, 128, 8, 4, 128);
    c1.s3 = mk(mean_u, tc1ruWl + 64 * 128, hu, tc1ruWr + 64 * 128, c1rubl + 64, u1 + 64, N_USERS,   128, 128, 8, 4, 128);
    c1.sp1 = GB_R; c1.sp2 = 2 * GB_R; c1.sp3 = 2 * GB_R + GB_U;

    GQuad c2;   // J=64 native: only two sides carry blocks
    c2.s0 = mk(mr2, tc2urWl, r1, tc2urWr, c2urbl, zr, N_RECIPES, 128, 128, 8, 4, 64);
    c2.s1 = mk(mu2, tc2ruWl, u1, tc2ruWr, c2rubl, zu, N_USERS,   128, 128, 8, 4, 64);
    c2.s2 = c2.s1; c2.s3 = c2.s1;
    c2.sp1 = GB_R; c2.sp2 = GB_R + GB_U; c2.sp3 = GB_R + GB_U;

    // #1 weight prep
    prep_weights<<<(W_TOTAL + 255) / 256, 256>>>(
        Wu, Wrec, c1urWl, c1urWr, c1ruWl, c1ruWr,
        c2urWl, c2urWr, c2ruWl, c2ruWr, wts);

    // #2-#3 CSR front
    zero_int2<<<(N_USERS + N_RECIPES + 255) / 256, 256>>>(cur_u, N_USERS, cur_r, N_RECIPES);
    count_deg<<<(NE + 255) / 256, 256>>>(edge_src, edge_dst, cur_u, cur_r, NE);

    // #4 combined input projections (ncu target)
    gemm_mma<false><<<PROJ_GRID, 256, SM_O>>>(proj);

    // CSR rest
    scan_chunks2<<<CH_U + CH_R, 1024>>>(cur_u, off_u, bs_u, N_USERS, CH_U,
                                        cur_r, off_r, bs_r, N_RECIPES);
    scan_bsums2<<<2, 32>>>(bs_u, CH_U, bs_r, CH_R);
    add_bsums2<<<CH_U + CH_R, 1024>>>(off_u, bs_u, N_USERS, CH_U,
                                      off_r, bs_r, N_RECIPES);
    copy_int2<<<(N_USERS + N_RECIPES + 255) / 256, 256>>>(cur_u, off_u, N_USERS,
                                                          cur_r, off_r, N_RECIPES);
    fill_adj<<<(NE + 255) / 256, 256>>>(edge_src, edge_dst, cur_u, cur_r, adj_u, adj_r, NE);

    // conv1
    aggregate_mean2<<<((N_RECIPES + N_USERS) * 32 + 255) / 256, 256>>>(
        hu, off_r, adj_r, mean_r, N_RECIPES,
        hr, off_u, adj_u, mean_u, N_USERS);
    gemm_mma<true><<<PROJ_GRID, 256, SM_O>>>(c1);

    // conv2
    aggregate_mean2<<<((N_RECIPES + N_USERS) * 32 + 255) / 256, 256>>>(
        u1, off_r, adj_r, mr2, N_RECIPES,
        r1, off_u, adj_u, mu2, N_USERS);
    gemm_mma<false><<<GB_R + GB_U, 256, SM_O>>>(c2);

    // decoder
    decoder_kernel<<<(NL + 7) / 8, 256>>>(zu, zr, lbl_src, lbl_dst, out, NL);
}